// round 2
// baseline (speedup 1.0000x reference)
#include <cuda_runtime.h>

#define O_TOTAL 16384
#define NB 64
#define HDIM 128
#define CDIM 32
#define OTILE 128

// Scratch (device globals — no allocation allowed)
__device__ float g_Aw[HDIM * NB];          // [h][b], A premultiplied by |W2[h]|
__device__ float g_Gw[O_TOTAL * HDIM];     // [tile][h][o_local], premultiplied by |W2[h]|

// ---------- packed f32x2 helpers ----------
__device__ __forceinline__ unsigned long long pack2(float x, float y) {
    unsigned long long u;
    asm("mov.b64 %0, {%1,%2};" : "=l"(u) : "f"(x), "f"(y));
    return u;
}
__device__ __forceinline__ void unpack2(unsigned long long u, float &x, float &y) {
    asm("mov.b64 {%0,%1}, %2;" : "=f"(x), "=f"(y) : "l"(u));
}
__device__ __forceinline__ unsigned long long add2(unsigned long long a, unsigned long long b) {
    unsigned long long d;
    asm("add.rn.f32x2 %0, %1, %2;" : "=l"(d) : "l"(a), "l"(b));
    return d;
}
__device__ __forceinline__ unsigned long long fma2(unsigned long long a, unsigned long long b, unsigned long long c) {
    unsigned long long d;
    asm("fma.rn.f32x2 %0, %1, %2, %3;" : "=l"(d) : "l"(a), "l"(b), "l"(c));
    return d;
}
__device__ __forceinline__ unsigned long long relu2(unsigned long long v) {
    float x, y;
    unpack2(v, x, y);
    x = fmaxf(x, 0.0f);
    y = fmaxf(y, 0.0f);
    return pack2(x, y);
}

// =====================================================================
// Kernel 1: prep. CTAs 0..127 compute Gw tiles (GEMM K=32 + bias, x|w|).
//           CTAs 128..143 compute pz = relu(z@Wz+bz) then Aw h-tile.
// =====================================================================
#define PREP_SMEM 58368

__global__ void __launch_bounds__(512) k_prep(
    const float* __restrict__ z,  const float* __restrict__ fe,
    const float* __restrict__ fb, const float* __restrict__ Wz,
    const float* __restrict__ bz, const float* __restrict__ W1,
    const float* __restrict__ b1, const float* __restrict__ W2)
{
    extern __shared__ float sm[];
    int tid = threadIdx.x;

    if (blockIdx.x < 128) {
        // ---- Gw tile: o in [t*128, t*128+128) ----
        int t = blockIdx.x;
        float* W1fs = sm;                  // [c][h]  32x128
        float* fes  = sm + 32 * 128;       // [c][o]  pitch 129 (conflict-free)

        for (int i = tid; i < 32 * 128; i += 512) W1fs[i] = W1[128 * 128 + i];
        for (int i = tid; i < 128 * 32; i += 512) {
            int o = i >> 5, c = i & 31;
            fes[c * 129 + o] = fe[(t * 128 + o) * 32 + c];
        }
        __syncthreads();

        int ol = tid & 127;          // o_local
        int hc = tid >> 7;           // h-chunk 0..3, h in [hc*32, hc*32+32)
        unsigned long long acc[16];
#pragma unroll
        for (int j = 0; j < 16; j++) acc[j] = 0ull;

#pragma unroll 4
        for (int c = 0; c < 32; c++) {
            float f = fes[c * 129 + ol];
            unsigned long long f2 = pack2(f, f);
            const unsigned long long* wrow =
                (const unsigned long long*)(W1fs + c * 128 + hc * 32);
#pragma unroll
            for (int j = 0; j < 16; j++)
                acc[j] = fma2(f2, wrow[j], acc[j]);
        }

        float fbv = fb[t * 128 + ol];
#pragma unroll
        for (int j = 0; j < 16; j++) {
            int h0 = hc * 32 + 2 * j;
            float ax, ay;
            unpack2(acc[j], ax, ay);
            float g0 = (ax + fbv * W1[160 * 128 + h0]     + b1[h0])     * fabsf(W2[h0]);
            float g1 = (ay + fbv * W1[160 * 128 + h0 + 1] + b1[h0 + 1]) * fabsf(W2[h0 + 1]);
            g_Gw[t * 16384 + h0 * 128 + ol]       = g0;
            g_Gw[t * 16384 + (h0 + 1) * 128 + ol] = g1;
        }
    } else {
        // ---- pz + Aw: CTA c handles h-tile [8c, 8c+8) ----
        int cta = blockIdx.x - 128;        // 0..15
        float* zs  = sm;                   // [b][k]  64x32
        float* Wzs = sm + 64 * 32;         // [k][h]  32x128
        float* bzs = Wzs + 32 * 128;       // [h]
        float* pzT = bzs + 128;            // [k][b]  pitch 65

        for (int i = tid; i < 64 * 32; i += 512)  zs[i]  = z[i];
        for (int i = tid; i < 32 * 128; i += 512) Wzs[i] = Wz[i];
        for (int i = tid; i < 128; i += 512)      bzs[i] = bz[i];
        __syncthreads();

        // pz = relu(z@Wz + bz), stored transposed [k][b] with pad 65
        for (int i = tid; i < 64 * 128; i += 512) {
            int b = i >> 7, hh = i & 127;
            float a = bzs[hh];
#pragma unroll
            for (int k = 0; k < 32; k++)
                a += zs[b * 32 + k] * Wzs[k * 128 + hh];
            pzT[hh * 65 + b] = fmaxf(a, 0.0f);
        }
        __syncthreads();

        // Aw[b,h] = (pz @ W1_h)[b,h] * |W2[h]|
        int h = cta * 8 + (tid >> 6);      // 8 h per CTA
        int b = tid & 63;
        float a = 0.0f;
#pragma unroll 8
        for (int k = 0; k < 128; k++)
            a += pzT[k * 65 + b] * W1[k * 128 + h];
        g_Aw[h * 64 + b] = a * fabsf(W2[h]);
    }
}

// =====================================================================
// Kernel 2: main. CTA t handles o-tile [t*128, t*128+128), all 64 b.
// out[b,o] = sum_h sgn(w[h]) * max(Aw[b,h] + Gw[o,h], 0) + b2
// =====================================================================
#define MAIN_SMEM (128 * 64 * 8 + 128 * 128 * 4 + 128 * 8)   // 132096

__global__ void __launch_bounds__(512) k_main(
    const float* __restrict__ W2, const float* __restrict__ b2,
    float* __restrict__ out)
{
    extern __shared__ float sm[];
    unsigned long long* As2 = (unsigned long long*)sm;         // [h][b] dup pairs, 64KB
    float* Gs = sm + 2 * 128 * 64;                             // [h][o], 64KB
    unsigned long long* s2 = (unsigned long long*)(Gs + 128 * 128);  // sgn dup pairs

    int tid = threadIdx.x;
    int t = blockIdx.x;

    // preamble: load A (duplicated pairs), G tile, signs
    for (int i = tid; i < 128 * 64; i += 512) {
        float a = g_Aw[i];
        As2[i] = pack2(a, a);
    }
    {
        const float4* gsrc = (const float4*)(g_Gw + t * 16384);
        float4* gdst = (float4*)Gs;
        for (int i = tid; i < 128 * 128 / 4; i += 512) gdst[i] = gsrc[i];
    }
    if (tid < 128) {
        float w = W2[tid];
        float s = (w >= 0.0f) ? 1.0f : -1.0f;
        s2[tid] = pack2(s, s);
    }
    __syncthreads();

    int og = tid & 31;           // o-group: o_local = og*4 .. og*4+3
    int bg = tid >> 5;           // b-group: b = bg*4 .. bg*4+3
    int o0 = og * 4, b0 = bg * 4;

    unsigned long long acc[4][2];
#pragma unroll
    for (int i = 0; i < 4; i++) { acc[i][0] = 0ull; acc[i][1] = 0ull; }

    const ulonglong2* Av = (const ulonglong2*)As2;   // 32 entries per h (64 dup-pairs)
    const ulonglong2* Gv = (const ulonglong2*)Gs;    // 32 entries per h (128 floats)

#pragma unroll 8
    for (int h = 0; h < 128; h++) {
        ulonglong2 a01 = Av[h * 32 + bg * 2];        // {a(b0),a(b0)},{a(b0+1),a(b0+1)}
        ulonglong2 a23 = Av[h * 32 + bg * 2 + 1];
        ulonglong2 g   = Gv[h * 32 + og];            // g.x={g(o0),g(o0+1)}, g.y={g(o0+2),g(o0+3)}
        unsigned long long sp = s2[h];
        unsigned long long ap0 = a01.x, ap1 = a01.y, ap2 = a23.x, ap3 = a23.y;

        unsigned long long v;
        v = relu2(add2(ap0, g.x)); acc[0][0] = fma2(v, sp, acc[0][0]);
        v = relu2(add2(ap0, g.y)); acc[0][1] = fma2(v, sp, acc[0][1]);
        v = relu2(add2(ap1, g.x)); acc[1][0] = fma2(v, sp, acc[1][0]);
        v = relu2(add2(ap1, g.y)); acc[1][1] = fma2(v, sp, acc[1][1]);
        v = relu2(add2(ap2, g.x)); acc[2][0] = fma2(v, sp, acc[2][0]);
        v = relu2(add2(ap2, g.y)); acc[2][1] = fma2(v, sp, acc[2][1]);
        v = relu2(add2(ap3, g.x)); acc[3][0] = fma2(v, sp, acc[3][0]);
        v = relu2(add2(ap3, g.y)); acc[3][1] = fma2(v, sp, acc[3][1]);
    }

    float b2v = b2[0];
#pragma unroll
    for (int i = 0; i < 4; i++) {
        float4 r;
        unpack2(acc[i][0], r.x, r.y);
        unpack2(acc[i][1], r.z, r.w);
        r.x += b2v; r.y += b2v; r.z += b2v; r.w += b2v;
        *(float4*)(out + (b0 + i) * O_TOTAL + t * 128 + o0) = r;
    }
}

extern "C" void kernel_launch(void* const* d_in, const int* in_sizes, int n_in,
                              void* d_out, int out_size) {
    (void)in_sizes; (void)n_in; (void)out_size;
    const float* z  = (const float*)d_in[0];
    const float* fe = (const float*)d_in[1];
    const float* fb = (const float*)d_in[2];
    const float* Wz = (const float*)d_in[3];
    const float* bz = (const float*)d_in[4];
    const float* W1 = (const float*)d_in[5];
    const float* b1 = (const float*)d_in[6];
    const float* W2 = (const float*)d_in[7];
    const float* b2 = (const float*)d_in[8];
    float* out = (float*)d_out;

    cudaFuncSetAttribute(k_prep, cudaFuncAttributeMaxDynamicSharedMemorySize, PREP_SMEM);
    cudaFuncSetAttribute(k_main, cudaFuncAttributeMaxDynamicSharedMemorySize, MAIN_SMEM);

    k_prep<<<144, 512, PREP_SMEM>>>(z, fe, fb, Wz, bz, W1, b1, W2);
    k_main<<<128, 512, MAIN_SMEM>>>(W2, b2, out);
}